// round 15
// baseline (speedup 1.0000x reference)
#include <cuda_runtime.h>
#include <cuda_bf16.h>

// RippleNet, two-phase:
//  K1 (qbuild): q[b][r] = R[r]^T item_b for all (b,r), float4-vectorized,
//               written to __device__ scratch g_Q; item rows stashed in g_I.
//  K2 (main):   per-b block; Q tile arrives as ONE coalesced LDG.128/thread
//               (no per-block R re-read), head/tail rows gathered 4-lanes-per-
//               row and prefetched before the single data barrier.
//
// H=2, B=2048, M=64, D=16, N_ENT=500000, N_REL=32.

#define NUM_B   2048
#define NUM_M   64
#define DIM     16
#define NUM_REL 32
#define QPAD    20      // padded q_sh rows (80B) to spread LDS banks
#define THREADS 128

__device__ __align__(16) float g_Q[NUM_B * NUM_REL * DIM];  // 4 MB scratch
__device__ __align__(16) float g_I[NUM_B * DIM];            // 128 KB

// ---------------- K1: q[b][r][j] = sum_i rel[r][i][j] * item_b[i] ----------
// 256 thr = 2 b's x (32 r x 4 quarter-rows). R rows read as float4 (coalesced
// 64B per 4-lane group), item broadcast from shared.
__global__ __launch_bounds__(256, 8)
void qbuild_kernel(const int*   __restrict__ items,
                   const float* __restrict__ ent,
                   const float* __restrict__ rel)
{
    __shared__ __align__(16) float item_s[2][DIM];
    const int tid = threadIdx.x;
    const int bl  = tid >> 7;          // which of the 2 b's
    const int t   = tid & 127;
    const int r   = t >> 2;            // relation 0..31
    const int c   = t & 3;             // quarter-row 0..3
    const int b   = blockIdx.x * 2 + bl;

    if (t < 4) {                       // 4 lanes fetch the item row
        const int it = items[b];
        const float4 v = ((const float4*)ent)[(size_t)it * 4 + t];
        ((float4*)item_s[bl])[t] = v;
        ((float4*)g_I)[b * 4 + t] = v;
    }
    __syncthreads();

    // rel[r][i][4c..4c+3] as float4: index r*64 + i*4 + c
    const float4* Rv = (const float4*)rel + r * 64 + c;
    float4 acc = make_float4(0.f, 0.f, 0.f, 0.f);
    #pragma unroll
    for (int i = 0; i < DIM; ++i) {
        const float4 rv = Rv[i * 4];
        const float  w  = item_s[bl][i];
        acc.x = fmaf(rv.x, w, acc.x);
        acc.y = fmaf(rv.y, w, acc.y);
        acc.z = fmaf(rv.z, w, acc.z);
        acc.w = fmaf(rv.w, w, acc.w);
    }
    // q[b][r][4c..]: float4 index b*128 + r*4 + c == b*128 + t  (coalesced)
    ((float4*)g_Q)[b * 128 + t] = acc;
}

// ---------------- K2: gathers + softmax + aggregation ----------------------
__global__ __launch_bounds__(THREADS, 8)
void ripplenet_main(const int*   __restrict__ heads,
                    const int*   __restrict__ rels,
                    const int*   __restrict__ tails,
                    const float* __restrict__ ent,
                    float*       __restrict__ out)
{
    __shared__ __align__(16) float q_sh[NUM_REL][QPAD];
    __shared__ __align__(16) float item_sh[DIM];
    __shared__ float logit_sh[2][NUM_M];
    __shared__ float user_sh[4][DIM];

    const int tid  = threadIdx.x;
    const int warp = tid >> 5;
    const int lane = tid & 31;
    const int hop  = warp >> 1;     // 0/1
    const int half = warp & 1;      // which 32-memory half
    const int b    = blockIdx.x;
    const int g    = lane >> 2;     // row group 0..7
    const int c    = lane & 3;      // float4 chunk within row

    const float4* ent4 = (const float4*)ent;
    const unsigned FULL = 0xffffffffu;

    // ---- indices: coalesced, lane owns memory (half*32 + lane) ----
    const int base = (hop * NUM_B + b) * NUM_M + half * 32 + lane;
    const int tidx = tails[base];
    const int hidx = heads[base];
    const int ridx = rels[base];

    // ---- distribute row indices, then front-batch all gathers ----
    int hr[4], tr[4];
    #pragma unroll
    for (int k = 0; k < 4; ++k) {
        hr[k] = __shfl_sync(FULL, hidx, k * 8 + g);
        tr[k] = __shfl_sync(FULL, tidx, k * 8 + g);
    }
    float4 hv[4], tv[4];
    #pragma unroll
    for (int k = 0; k < 4; ++k) {
        hv[k] = ent4[(size_t)hr[k] * 4 + c];
        tv[k] = ent4[(size_t)tr[k] * 4 + c];
    }

    // ---- block data: Q tile (2KB contiguous) + item row, no index dep ----
    const float4 qv4 = ((const float4*)g_Q)[b * 128 + tid];   // coalesced
    if (warp == 0 && lane < 4)
        ((float4*)item_sh)[lane] = ((const float4*)g_I)[b * 4 + lane];
    {
        const int qr = tid >> 2, qc = tid & 3;
        *(float4*)&q_sh[qr][4 * qc] = qv4;
    }
    __syncthreads();                  // q_sh + item_sh ready

    // ---- logits from prefetched head registers + q_sh, quad reduce ----
    #pragma unroll
    for (int k = 0; k < 4; ++k) {
        const int src = k * 8 + g;
        const int rr  = __shfl_sync(FULL, ridx, src);
        const float4 qv = *(const float4*)&q_sh[rr][4 * c];
        float p = hv[k].x * qv.x + hv[k].y * qv.y
                + hv[k].z * qv.z + hv[k].w * qv.w;
        p += __shfl_xor_sync(FULL, p, 1);
        p += __shfl_xor_sync(FULL, p, 2);
        if (c == 0) logit_sh[hop][half * 32 + src] = p;
    }
    __syncthreads();                  // both halves' logits visible

    // ---- softmax over M=64 (redundant in both warps of the hop) ----
    // logits are O(0.1): skip max-subtraction, exp exact here.
    const float l0 = logit_sh[hop][lane];
    const float l1 = logit_sh[hop][lane + 32];
    const float e0 = __expf(l0), e1 = __expf(l1);
    float s = e0 + e1;
    #pragma unroll
    for (int o = 16; o >= 1; o >>= 1)
        s += __shfl_xor_sync(FULL, s, o);
    const float inv = __frcp_rn(s);
    const float myp = (half == 0 ? e0 : e1) * inv;

    // ---- tail accumulate on prefetched registers ----
    float4 acc = make_float4(0.f, 0.f, 0.f, 0.f);
    #pragma unroll
    for (int k = 0; k < 4; ++k) {
        const float p = __shfl_sync(FULL, myp, k * 8 + g);
        acc.x = fmaf(p, tv[k].x, acc.x);
        acc.y = fmaf(p, tv[k].y, acc.y);
        acc.z = fmaf(p, tv[k].z, acc.z);
        acc.w = fmaf(p, tv[k].w, acc.w);
    }
    #pragma unroll
    for (int o = 4; o <= 16; o <<= 1) {            // combine the 8 row-groups
        acc.x += __shfl_xor_sync(FULL, acc.x, o);
        acc.y += __shfl_xor_sync(FULL, acc.y, o);
        acc.z += __shfl_xor_sync(FULL, acc.z, o);
        acc.w += __shfl_xor_sync(FULL, acc.w, o);
    }
    if (lane < 4) *(float4*)&user_sh[warp][4 * lane] = acc;
    __syncthreads();

    // ---- combine 4 warp partials, dot with item, sigmoid ----
    if (warp == 0 && lane < DIM) {
        const float ur = user_sh[0][lane] + user_sh[1][lane]
                       + user_sh[2][lane] + user_sh[3][lane];
        float d = ur * item_sh[lane];
        #pragma unroll
        for (int o = 8; o >= 1; o >>= 1)
            d += __shfl_xor_sync(0x0000ffffu, d, o, 16);
        if (lane == 0) out[b] = __frcp_rn(1.f + __expf(-d));
    }
}

extern "C" void kernel_launch(void* const* d_in, const int* in_sizes, int n_in,
                              void* d_out, int out_size)
{
    const int*   items = (const int*)  d_in[0];
    const int*   heads = (const int*)  d_in[1];
    const int*   rels  = (const int*)  d_in[2];
    const int*   tails = (const int*)  d_in[3];
    const float* ent   = (const float*)d_in[4];
    const float* rel   = (const float*)d_in[5];
    float*       out   = (float*)d_out;

    qbuild_kernel<<<NUM_B / 2, 256>>>(items, ent, rel);
    ripplenet_main<<<NUM_B, THREADS>>>(heads, rels, tails, ent, out);
}

// round 16
// speedup vs baseline: 1.1102x; 1.1102x over previous
#include <cuda_runtime.h>
#include <cuda_bf16.h>

// RippleNet single-kernel: (R h).item == (R^T item).h -> q[r] = R[r]^T item
// per b (32 rels); each memory's logit is a 16-dot.
//  - q-build vectorized: thread (r,c) computes float4 q[r][4c..] via 16
//    LDG.128 of the L1-resident R table (halves q-build instructions vs
//    scalar-column version).
//  - head+tail rows gathered 4-lanes-per-64B-row, front-batched into 8
//    in-flight LDG.128 before the q-build so the gather latency is hidden.
//  - tails held in registers across the softmax -> no second gather chain.
//
// H=2, B=2048, M=64, D=16, N_ENT=500000, N_REL=32.
// Block = 128 thr = 4 warps = (hop, half): 32 memories per warp. Grid = 2048.

#define NUM_B   2048
#define NUM_M   64
#define DIM     16
#define NUM_REL 32
#define QPAD    20      // 80B q_sh rows: 16B-aligned, banks cycle
#define THREADS 128

__global__ __launch_bounds__(THREADS, 8)
void ripplenet_kernel(const int*   __restrict__ items,
                      const int*   __restrict__ heads,
                      const int*   __restrict__ rels,
                      const int*   __restrict__ tails,
                      const float* __restrict__ ent,
                      const float* __restrict__ rel,
                      float*       __restrict__ out)
{
    __shared__ __align__(16) float q_sh[NUM_REL][QPAD];
    __shared__ __align__(16) float item_sh[DIM];
    __shared__ float logit_sh[2][NUM_M];
    __shared__ float user_sh[4][DIM];

    const int tid  = threadIdx.x;
    const int warp = tid >> 5;
    const int lane = tid & 31;
    const int hop  = warp >> 1;     // 0/1
    const int half = warp & 1;      // which 32-memory half
    const int b    = blockIdx.x;
    const int g    = lane >> 2;     // row group 0..7
    const int c    = lane & 3;      // float4 chunk within row

    const float4* ent4 = (const float4*)ent;
    const float4* rel4 = (const float4*)rel;
    const unsigned FULL = 0xffffffffu;

    // ---- indices: coalesced, lane owns memory (half*32 + lane) ----
    const int base = (hop * NUM_B + b) * NUM_M + half * 32 + lane;
    const int tidx = tails[base];
    const int hidx = heads[base];
    const int ridx = rels[base];

    // ---- item embedding -> shared (warp 0, 4 lanes x float4) ----
    if (warp == 0 && lane < 4) {
        const int it = items[b];
        ((float4*)item_sh)[lane] = ent4[(size_t)it * 4 + lane];
    }

    // ---- distribute row indices, then front-batch all 8 LDG.128 ----
    int hr[4], tr[4];
    #pragma unroll
    for (int k = 0; k < 4; ++k) {
        hr[k] = __shfl_sync(FULL, hidx, k * 8 + g);
        tr[k] = __shfl_sync(FULL, tidx, k * 8 + g);
    }
    float4 hv[4], tv[4];
    #pragma unroll
    for (int k = 0; k < 4; ++k) {
        hv[k] = ent4[(size_t)hr[k] * 4 + c];
        tv[k] = ent4[(size_t)tr[k] * 4 + c];
    }

    __syncthreads();                  // item_sh ready (gathers still in flight)

    // ---- q-build, vectorized: thread (qr,qc) -> q[qr][4qc..4qc+3] ----
    // 16 LDG.128 of L1-resident R + 4 broadcast LDS.128 of item + 64 FMA.
    {
        const int qr = tid >> 2;      // relation 0..31
        const int qc = tid & 3;       // quarter-row 0..3
        const float4* Rv = rel4 + qr * 64 + qc;   // rel[qr][i][4qc..] at i*4
        float4 acc = make_float4(0.f, 0.f, 0.f, 0.f);
        #pragma unroll
        for (int ih = 0; ih < 2; ++ih) {          // stage item 8 floats at a time
            const float4 ia = ((const float4*)item_sh)[2 * ih + 0];
            const float4 ib = ((const float4*)item_sh)[2 * ih + 1];
            const int i0 = 8 * ih;
            float4 rv;
            rv = Rv[(i0 + 0) * 4];
            acc.x = fmaf(rv.x, ia.x, acc.x); acc.y = fmaf(rv.y, ia.x, acc.y);
            acc.z = fmaf(rv.z, ia.x, acc.z); acc.w = fmaf(rv.w, ia.x, acc.w);
            rv = Rv[(i0 + 1) * 4];
            acc.x = fmaf(rv.x, ia.y, acc.x); acc.y = fmaf(rv.y, ia.y, acc.y);
            acc.z = fmaf(rv.z, ia.y, acc.z); acc.w = fmaf(rv.w, ia.y, acc.w);
            rv = Rv[(i0 + 2) * 4];
            acc.x = fmaf(rv.x, ia.z, acc.x); acc.y = fmaf(rv.y, ia.z, acc.y);
            acc.z = fmaf(rv.z, ia.z, acc.z); acc.w = fmaf(rv.w, ia.z, acc.w);
            rv = Rv[(i0 + 3) * 4];
            acc.x = fmaf(rv.x, ia.w, acc.x); acc.y = fmaf(rv.y, ia.w, acc.y);
            acc.z = fmaf(rv.z, ia.w, acc.z); acc.w = fmaf(rv.w, ia.w, acc.w);
            rv = Rv[(i0 + 4) * 4];
            acc.x = fmaf(rv.x, ib.x, acc.x); acc.y = fmaf(rv.y, ib.x, acc.y);
            acc.z = fmaf(rv.z, ib.x, acc.z); acc.w = fmaf(rv.w, ib.x, acc.w);
            rv = Rv[(i0 + 5) * 4];
            acc.x = fmaf(rv.x, ib.y, acc.x); acc.y = fmaf(rv.y, ib.y, acc.y);
            acc.z = fmaf(rv.z, ib.y, acc.z); acc.w = fmaf(rv.w, ib.y, acc.w);
            rv = Rv[(i0 + 6) * 4];
            acc.x = fmaf(rv.x, ib.z, acc.x); acc.y = fmaf(rv.y, ib.z, acc.y);
            acc.z = fmaf(rv.z, ib.z, acc.z); acc.w = fmaf(rv.w, ib.z, acc.w);
            rv = Rv[(i0 + 7) * 4];
            acc.x = fmaf(rv.x, ib.w, acc.x); acc.y = fmaf(rv.y, ib.w, acc.y);
            acc.z = fmaf(rv.z, ib.w, acc.z); acc.w = fmaf(rv.w, ib.w, acc.w);
        }
        *(float4*)&q_sh[qr][4 * qc] = acc;
    }
    __syncthreads();                  // q_sh ready

    // ---- logits from prefetched head registers + q_sh, quad reduce ----
    #pragma unroll
    for (int k = 0; k < 4; ++k) {
        const int src = k * 8 + g;
        const int rr  = __shfl_sync(FULL, ridx, src);
        const float4 qv = *(const float4*)&q_sh[rr][4 * c];
        float p = hv[k].x * qv.x + hv[k].y * qv.y
                + hv[k].z * qv.z + hv[k].w * qv.w;
        p += __shfl_xor_sync(FULL, p, 1);
        p += __shfl_xor_sync(FULL, p, 2);
        if (c == 0) logit_sh[hop][half * 32 + src] = p;
    }
    __syncthreads();                  // both halves' logits visible

    // ---- softmax over M=64 (redundant in both warps of the hop) ----
    // logits are O(0.1): skip max-subtraction, exp exact here.
    const float l0 = logit_sh[hop][lane];
    const float l1 = logit_sh[hop][lane + 32];
    const float e0 = __expf(l0), e1 = __expf(l1);
    float s = e0 + e1;
    #pragma unroll
    for (int o = 16; o >= 1; o >>= 1)
        s += __shfl_xor_sync(FULL, s, o);
    const float inv = __frcp_rn(s);
    const float myp = (half == 0 ? e0 : e1) * inv;

    // ---- tail accumulate on prefetched registers ----
    float4 acc = make_float4(0.f, 0.f, 0.f, 0.f);
    #pragma unroll
    for (int k = 0; k < 4; ++k) {
        const float p = __shfl_sync(FULL, myp, k * 8 + g);
        acc.x = fmaf(p, tv[k].x, acc.x);
        acc.y = fmaf(p, tv[k].y, acc.y);
        acc.z = fmaf(p, tv[k].z, acc.z);
        acc.w = fmaf(p, tv[k].w, acc.w);
    }
    #pragma unroll
    for (int o = 4; o <= 16; o <<= 1) {            // combine the 8 row-groups
        acc.x += __shfl_xor_sync(FULL, acc.x, o);
        acc.y += __shfl_xor_sync(FULL, acc.y, o);
        acc.z += __shfl_xor_sync(FULL, acc.z, o);
        acc.w += __shfl_xor_sync(FULL, acc.w, o);
    }
    if (lane < 4) *(float4*)&user_sh[warp][4 * lane] = acc;
    __syncthreads();

    // ---- combine 4 warp partials, dot with item, sigmoid ----
    if (warp == 0 && lane < DIM) {
        const float ur = user_sh[0][lane] + user_sh[1][lane]
                       + user_sh[2][lane] + user_sh[3][lane];
        float d = ur * item_sh[lane];
        #pragma unroll
        for (int o = 8; o >= 1; o >>= 1)
            d += __shfl_xor_sync(0x0000ffffu, d, o, 16);
        if (lane == 0) out[b] = __frcp_rn(1.f + __expf(-d));
    }
}

extern "C" void kernel_launch(void* const* d_in, const int* in_sizes, int n_in,
                              void* d_out, int out_size)
{
    const int*   items = (const int*)  d_in[0];
    const int*   heads = (const int*)  d_in[1];
    const int*   rels  = (const int*)  d_in[2];
    const int*   tails = (const int*)  d_in[3];
    const float* ent   = (const float*)d_in[4];
    const float* rel   = (const float*)d_in[5];
    float*       out   = (float*)d_out;

    ripplenet_kernel<<<NUM_B, THREADS>>>(items, heads, rels, tails, ent, rel, out);
}